// round 1
// baseline (speedup 1.0000x reference)
#include <cuda_runtime.h>

// Scalar accumulator in device global memory (no allocations allowed).
__device__ double g_spike_acc;

__global__ void spike_zero_kernel() { g_spike_acc = 0.0; }

__global__ void spike_finalize_kernel(float* out) {
    out[0] = (float)(0.5 * g_spike_acc);
}

// One warp per pixel (B*C*H*W), lanes map to time steps (contiguous axis).
// Linear recurrence syn_t = decay*syn_{t-1} + x_t computed via Kogge-Stone
// inclusive scan with weights decay^{2^k}; cross-chunk carry injected as
// decay^{lane+1} * carry.
__global__ void __launch_bounds__(256) spike_loss_kernel(
    const float* __restrict__ outputs,
    const float* __restrict__ target,
    const int* __restrict__ n_steps_p,
    const int* __restrict__ tau_p,
    long long n_total)
{
    const int   T       = *n_steps_p;
    const float tau     = (float)(*tau_p);
    const float inv_tau = 1.0f / tau;
    const float decay   = 1.0f - inv_tau;

    const int lane = threadIdx.x & 31;

    // Scan-step weights decay^(2^k)
    const float d1  = decay;
    const float d2  = d1 * d1;
    const float d4  = d2 * d2;
    const float d8  = d4 * d4;
    const float d16 = d8 * d8;
    // Carry weight: decay^(lane+1)
    const float dlane1 = __powf(decay, (float)(lane + 1));

    const long long pixels      = n_total / (long long)T;
    const int       warps_total = (gridDim.x * blockDim.x) >> 5;
    const int       warp_id     = (int)((blockIdx.x * blockDim.x + threadIdx.x) >> 5);

    float acc = 0.0f;

    for (long long p = warp_id; p < pixels; p += warps_total) {
        const float* tg = target  + p * (long long)T;
        const float* ob = outputs + p * (long long)T;

        float carry = 0.0f;
        for (int t0 = 0; t0 < T; t0 += 32) {
            const int  t     = t0 + lane;
            const bool valid = (t < T);

            float x = valid ? tg[t] : 0.0f;
            float o = valid ? ob[t] : 0.0f;

            // Inclusive scan: syn_lane = sum_{j<=lane} decay^{lane-j} * x_j
            float syn = x;
            float v;
            v = __shfl_up_sync(0xffffffffu, syn, 1);  if (lane >= 1)  syn = fmaf(d1,  v, syn);
            v = __shfl_up_sync(0xffffffffu, syn, 2);  if (lane >= 2)  syn = fmaf(d2,  v, syn);
            v = __shfl_up_sync(0xffffffffu, syn, 4);  if (lane >= 4)  syn = fmaf(d4,  v, syn);
            v = __shfl_up_sync(0xffffffffu, syn, 8);  if (lane >= 8)  syn = fmaf(d8,  v, syn);
            v = __shfl_up_sync(0xffffffffu, syn, 16); if (lane >= 16) syn = fmaf(d16, v, syn);

            // Inject carry from previous chunk: syn_{t0-1} = carry
            syn = fmaf(carry, dlane1, syn);

            if (valid) {
                const float d = o - syn * inv_tau;
                acc = fmaf(d, d, acc);
            }

            // Carry for the next chunk (only consumed when the current chunk
            // was full, in which case lane 31 holds syn_{t0+31}).
            carry = __shfl_sync(0xffffffffu, syn, 31);
        }
    }

    // Warp reduction
    #pragma unroll
    for (int off = 16; off; off >>= 1)
        acc += __shfl_down_sync(0xffffffffu, acc, off);

    __shared__ float warp_sums[8];
    const int wib = threadIdx.x >> 5;
    if (lane == 0) warp_sums[wib] = acc;
    __syncthreads();

    if (wib == 0) {
        const int nw = blockDim.x >> 5;
        float s = (lane < nw) ? warp_sums[lane] : 0.0f;
        #pragma unroll
        for (int off = 16; off; off >>= 1)
            s += __shfl_down_sync(0xffffffffu, s, off);
        if (lane == 0) atomicAdd(&g_spike_acc, (double)s);
    }
}

extern "C" void kernel_launch(void* const* d_in, const int* in_sizes, int n_in,
                              void* d_out, int out_size)
{
    const float* outputs = (const float*)d_in[0];
    const float* target  = (const float*)d_in[1];
    const int*   n_steps = (const int*)d_in[2];
    const int*   tau_s   = (const int*)d_in[3];
    float*       out     = (float*)d_out;

    const long long n_total = (long long)in_sizes[0];

    spike_zero_kernel<<<1, 1>>>();

    const int threads = 256;
    const int blocks  = 148 * 8;  // one full wave at max occupancy; grid-stride covers the rest
    spike_loss_kernel<<<blocks, threads>>>(outputs, target, n_steps, tau_s, n_total);

    spike_finalize_kernel<<<1, 1>>>(out);
}

// round 4
// speedup vs baseline: 1.6020x; 1.6020x over previous
#include <cuda_runtime.h>

#define MAX_BLOCKS 2048
__device__ float g_partials[MAX_BLOCKS];

// ---------------------------------------------------------------------------
// Loss = 0.5 * sum( (outputs - psp(target))^2 ), psp = leaky integrator over
// the contiguous trailing axis T:  syn_t = decay*syn_{t-1} + x_t, out = syn/tau.
//
// Layout: [pixel, T] with T contiguous. One warp per pixel; lane l owns a
// float4 covering t = 4l..4l+3. Linear recurrence via: serial 4-elem local
// scan per lane, Kogge-Stone warp scan of lane carries with ratio decay^4,
// exclusive-prefix injection. Two adjacent pixels per warp iteration for MLP.
// ---------------------------------------------------------------------------
__global__ void __launch_bounds__(256) spike_loss_kernel(
    const float* __restrict__ outputs,
    const float* __restrict__ target,
    const int* __restrict__ n_steps_p,
    const int* __restrict__ tau_p,
    long long n_total)
{
    const int   T       = *n_steps_p;
    const float tau     = (float)(*tau_p);
    const float inv_tau = 1.0f / tau;
    const float decay   = 1.0f - inv_tau;

    const int lane = threadIdx.x & 31;
    const unsigned FULL = 0xffffffffu;

    const long long pixels      = n_total / (long long)T;
    const int       warps_total = (gridDim.x * blockDim.x) >> 5;
    const int       warp_id     = (int)((blockIdx.x * blockDim.x + threadIdx.x) >> 5);

    float acc = 0.0f;

    if ((T & 3) == 0) {
        // ---------------- vectorized float4 path ----------------
        const int TV = T >> 2;                 // float4 count per row

        const float w1 = decay;
        const float w2 = decay * decay;
        const float w3 = w2 * decay;
        const float q  = w2 * w2;              // decay^4  (warp-scan ratio)
        const float q1  = q;
        const float q2  = q1 * q1;
        const float q4  = q2 * q2;
        const float q8  = q4 * q4;
        const float q16 = q8 * q8;
        const float qlane = __powf(q, (float)lane);   // decay^(4*lane): cross-chunk carry weight

        auto do_pixel = [&](float4 x, float4 o, bool valid, float& carry,
                            int last_lane, bool more) {
            // local inclusive scan (4 elems, lat-4 FFMA chain)
            float s0 = x.x;
            float s1 = fmaf(decay, s0, x.y);
            float s2 = fmaf(decay, s1, x.z);
            float s3 = fmaf(decay, s2, x.w);

            // warp inclusive scan of lane carries (ratio q)
            float c = valid ? s3 : 0.0f;
            float v;
            v = __shfl_up_sync(FULL, c, 1);  if (lane >= 1)  c = fmaf(q1,  v, c);
            v = __shfl_up_sync(FULL, c, 2);  if (lane >= 2)  c = fmaf(q2,  v, c);
            v = __shfl_up_sync(FULL, c, 4);  if (lane >= 4)  c = fmaf(q4,  v, c);
            v = __shfl_up_sync(FULL, c, 8);  if (lane >= 8)  c = fmaf(q8,  v, c);
            v = __shfl_up_sync(FULL, c, 16); if (lane >= 16) c = fmaf(q16, v, c);

            // exclusive prefix + cross-chunk carry
            float pref = __shfl_up_sync(FULL, c, 1);
            if (lane == 0) pref = 0.0f;
            pref = fmaf(carry, qlane, pref);

            s0 = fmaf(pref, w1, s0);
            s1 = fmaf(pref, w2, s1);
            s2 = fmaf(pref, w3, s2);
            s3 = fmaf(pref, q,  s3);

            if (valid) {
                float e0 = o.x - s0 * inv_tau;
                float e1 = o.y - s1 * inv_tau;
                float e2 = o.z - s2 * inv_tau;
                float e3 = o.w - s3 * inv_tau;
                acc = fmaf(e0, e0, acc);
                acc = fmaf(e1, e1, acc);
                acc = fmaf(e2, e2, acc);
                acc = fmaf(e3, e3, acc);
            }
            if (more)
                carry = __shfl_sync(FULL, s3, last_lane);
        };

        const long long stride2 = (long long)warps_total * 2;
        for (long long p = (long long)warp_id * 2; p < pixels; p += stride2) {
            const long long pB  = p + 1;
            const bool hasB     = (pB < pixels);

            const float4* tgA = (const float4*)(target  + p  * (long long)T);
            const float4* obA = (const float4*)(outputs + p  * (long long)T);
            const float4* tgB = (const float4*)(target  + pB * (long long)T);
            const float4* obB = (const float4*)(outputs + pB * (long long)T);

            float carryA = 0.0f, carryB = 0.0f;
            for (int c4 = 0; c4 < TV; c4 += 32) {
                const int  l4     = c4 + lane;
                const bool validA = (l4 < TV);
                const bool validB = validA && hasB;
                const bool more   = (c4 + 32 < TV);
                const int  last   = more ? 31 : (TV - c4 - 1);

                const float4 z = make_float4(0.f, 0.f, 0.f, 0.f);
                // issue all loads before any scan work (MLP = 4 wide loads)
                float4 xA = validA ? tgA[l4] : z;
                float4 oA = validA ? obA[l4] : z;
                float4 xB = validB ? tgB[l4] : z;
                float4 oB = validB ? obB[l4] : z;

                do_pixel(xA, oA, validA, carryA, last, more);
                do_pixel(xB, oB, validB, carryB, last, more);
            }
        }
    } else {
        // ---------------- generic scalar fallback ----------------
        const float d1  = decay;
        const float d2  = d1 * d1;
        const float d4  = d2 * d2;
        const float d8  = d4 * d4;
        const float d16 = d8 * d8;
        const float dlane1 = __powf(decay, (float)(lane + 1));

        for (long long p = warp_id; p < pixels; p += warps_total) {
            const float* tg = target  + p * (long long)T;
            const float* ob = outputs + p * (long long)T;
            float carry = 0.0f;
            for (int t0 = 0; t0 < T; t0 += 32) {
                const int  t     = t0 + lane;
                const bool valid = (t < T);
                float x = valid ? tg[t] : 0.0f;
                float o = valid ? ob[t] : 0.0f;
                float syn = x, v;
                v = __shfl_up_sync(FULL, syn, 1);  if (lane >= 1)  syn = fmaf(d1,  v, syn);
                v = __shfl_up_sync(FULL, syn, 2);  if (lane >= 2)  syn = fmaf(d2,  v, syn);
                v = __shfl_up_sync(FULL, syn, 4);  if (lane >= 4)  syn = fmaf(d4,  v, syn);
                v = __shfl_up_sync(FULL, syn, 8);  if (lane >= 8)  syn = fmaf(d8,  v, syn);
                v = __shfl_up_sync(FULL, syn, 16); if (lane >= 16) syn = fmaf(d16, v, syn);
                syn = fmaf(carry, dlane1, syn);
                if (valid) {
                    const float d = o - syn * inv_tau;
                    acc = fmaf(d, d, acc);
                }
                carry = __shfl_sync(FULL, syn, 31);
            }
        }
    }

    // warp reduction
    #pragma unroll
    for (int off = 16; off; off >>= 1)
        acc += __shfl_down_sync(FULL, acc, off);

    __shared__ float warp_sums[8];
    const int wib = threadIdx.x >> 5;
    if (lane == 0) warp_sums[wib] = acc;
    __syncthreads();

    if (wib == 0) {
        const int nw = blockDim.x >> 5;
        float s = (lane < nw) ? warp_sums[lane] : 0.0f;
        #pragma unroll
        for (int off = 16; off; off >>= 1)
            s += __shfl_down_sync(FULL, s, off);
        if (lane == 0) g_partials[blockIdx.x] = s;   // deterministic overwrite; no zero pass
    }
}

__global__ void spike_finalize_kernel(float* out, int nblocks) {
    const unsigned FULL = 0xffffffffu;
    double s = 0.0;
    for (int i = threadIdx.x; i < nblocks; i += blockDim.x)
        s += (double)g_partials[i];
    #pragma unroll
    for (int off = 16; off; off >>= 1)
        s += __shfl_down_sync(FULL, s, off);

    __shared__ double ws[8];
    const int lane = threadIdx.x & 31;
    const int wib  = threadIdx.x >> 5;
    if (lane == 0) ws[wib] = s;
    __syncthreads();
    if (wib == 0) {
        const int nw = blockDim.x >> 5;
        double t = (lane < nw) ? ws[lane] : 0.0;
        #pragma unroll
        for (int off = 16; off; off >>= 1)
            t += __shfl_down_sync(FULL, t, off);
        if (lane == 0) out[0] = (float)(0.5 * t);
    }
}

extern "C" void kernel_launch(void* const* d_in, const int* in_sizes, int n_in,
                              void* d_out, int out_size)
{
    const float* outputs = (const float*)d_in[0];
    const float* target  = (const float*)d_in[1];
    const int*   n_steps = (const int*)d_in[2];
    const int*   tau_s   = (const int*)d_in[3];
    float*       out     = (float*)d_out;

    const long long n_total = (long long)in_sizes[0];

    const int threads = 256;
    const int blocks  = 148 * 8;   // 1184 <= MAX_BLOCKS
    spike_loss_kernel<<<blocks, threads>>>(outputs, target, n_steps, tau_s, n_total);
    spike_finalize_kernel<<<1, 256>>>(out, blocks);
}

// round 5
// speedup vs baseline: 1.6897x; 1.0547x over previous
#include <cuda_runtime.h>

#define MAX_BLOCKS 2048
__device__ float        g_partials[MAX_BLOCKS];
__device__ unsigned int g_ticket;          // 0 at load; last block resets to 0 each launch

// ---------------------------------------------------------------------------
// Loss = 0.5 * sum( (outputs - psp(target))^2 ), psp = leaky integrator over
// the contiguous trailing axis T:  syn_t = decay*syn_{t-1} + x_t, out = syn/tau.
//
// One warp per pixel; lane l owns a float4 covering t = 4l..4l+3. Linear
// recurrence via serial 4-elem local scan per lane + Kogge-Stone warp scan of
// lane carries (ratio decay^4) + exclusive-prefix injection. Two adjacent
// pixels per warp iteration for MLP. Single kernel: last block reduces the
// per-block partials and writes the scalar (no second launch).
// ---------------------------------------------------------------------------
__global__ void __launch_bounds__(256) spike_loss_kernel(
    const float* __restrict__ outputs,
    const float* __restrict__ target,
    const int* __restrict__ n_steps_p,
    const int* __restrict__ tau_p,
    long long n_total,
    float* __restrict__ out)
{
    const int   T       = *n_steps_p;
    const float tau     = (float)(*tau_p);
    const float inv_tau = 1.0f / tau;
    const float decay   = 1.0f - inv_tau;

    const int lane = threadIdx.x & 31;
    const unsigned FULL = 0xffffffffu;

    const long long pixels      = n_total / (long long)T;
    const int       warps_total = (gridDim.x * blockDim.x) >> 5;
    const int       warp_id     = (int)((blockIdx.x * blockDim.x + threadIdx.x) >> 5);

    float acc = 0.0f;

    if ((T & 3) == 0) {
        // ---------------- vectorized float4 path ----------------
        const int TV = T >> 2;

        const float w1 = decay;
        const float w2 = decay * decay;
        const float w3 = w2 * decay;
        const float q  = w2 * w2;              // decay^4 (warp-scan ratio)
        const float q1  = q;
        const float q2  = q1 * q1;
        const float q4  = q2 * q2;
        const float q8  = q4 * q4;
        const float q16 = q8 * q8;
        const float qlane = __powf(q, (float)lane);   // decay^(4*lane)

        auto do_pixel = [&](float4 x, float4 o, bool valid, float& carry,
                            int last_lane, bool more) {
            float s0 = x.x;
            float s1 = fmaf(decay, s0, x.y);
            float s2 = fmaf(decay, s1, x.z);
            float s3 = fmaf(decay, s2, x.w);

            float c = valid ? s3 : 0.0f;
            float v;
            v = __shfl_up_sync(FULL, c, 1);  if (lane >= 1)  c = fmaf(q1,  v, c);
            v = __shfl_up_sync(FULL, c, 2);  if (lane >= 2)  c = fmaf(q2,  v, c);
            v = __shfl_up_sync(FULL, c, 4);  if (lane >= 4)  c = fmaf(q4,  v, c);
            v = __shfl_up_sync(FULL, c, 8);  if (lane >= 8)  c = fmaf(q8,  v, c);
            v = __shfl_up_sync(FULL, c, 16); if (lane >= 16) c = fmaf(q16, v, c);

            float pref = __shfl_up_sync(FULL, c, 1);
            if (lane == 0) pref = 0.0f;
            pref = fmaf(carry, qlane, pref);

            s0 = fmaf(pref, w1, s0);
            s1 = fmaf(pref, w2, s1);
            s2 = fmaf(pref, w3, s2);
            s3 = fmaf(pref, q,  s3);

            if (valid) {
                float e0 = o.x - s0 * inv_tau;
                float e1 = o.y - s1 * inv_tau;
                float e2 = o.z - s2 * inv_tau;
                float e3 = o.w - s3 * inv_tau;
                acc = fmaf(e0, e0, acc);
                acc = fmaf(e1, e1, acc);
                acc = fmaf(e2, e2, acc);
                acc = fmaf(e3, e3, acc);
            }
            if (more)
                carry = __shfl_sync(FULL, s3, last_lane);
        };

        const long long stride2 = (long long)warps_total * 2;
        for (long long p = (long long)warp_id * 2; p < pixels; p += stride2) {
            const long long pB  = p + 1;
            const bool hasB     = (pB < pixels);

            const float4* tgA = (const float4*)(target  + p  * (long long)T);
            const float4* obA = (const float4*)(outputs + p  * (long long)T);
            const float4* tgB = (const float4*)(target  + pB * (long long)T);
            const float4* obB = (const float4*)(outputs + pB * (long long)T);

            float carryA = 0.0f, carryB = 0.0f;
            for (int c4 = 0; c4 < TV; c4 += 32) {
                const int  l4     = c4 + lane;
                const bool validA = (l4 < TV);
                const bool validB = validA && hasB;
                const bool more   = (c4 + 32 < TV);
                const int  last   = more ? 31 : (TV - c4 - 1);

                const float4 z = make_float4(0.f, 0.f, 0.f, 0.f);
                float4 xA = validA ? tgA[l4] : z;
                float4 oA = validA ? obA[l4] : z;
                float4 xB = validB ? tgB[l4] : z;
                float4 oB = validB ? obB[l4] : z;

                do_pixel(xA, oA, validA, carryA, last, more);
                do_pixel(xB, oB, validB, carryB, last, more);
            }
        }
    } else {
        // ---------------- generic scalar fallback ----------------
        const float d1  = decay;
        const float d2  = d1 * d1;
        const float d4  = d2 * d2;
        const float d8  = d4 * d4;
        const float d16 = d8 * d8;
        const float dlane1 = __powf(decay, (float)(lane + 1));

        for (long long p = warp_id; p < pixels; p += warps_total) {
            const float* tg = target  + p * (long long)T;
            const float* ob = outputs + p * (long long)T;
            float carry = 0.0f;
            for (int t0 = 0; t0 < T; t0 += 32) {
                const int  t     = t0 + lane;
                const bool valid = (t < T);
                float x = valid ? tg[t] : 0.0f;
                float o = valid ? ob[t] : 0.0f;
                float syn = x, v;
                v = __shfl_up_sync(FULL, syn, 1);  if (lane >= 1)  syn = fmaf(d1,  v, syn);
                v = __shfl_up_sync(FULL, syn, 2);  if (lane >= 2)  syn = fmaf(d2,  v, syn);
                v = __shfl_up_sync(FULL, syn, 4);  if (lane >= 4)  syn = fmaf(d4,  v, syn);
                v = __shfl_up_sync(FULL, syn, 8);  if (lane >= 8)  syn = fmaf(d8,  v, syn);
                v = __shfl_up_sync(FULL, syn, 16); if (lane >= 16) syn = fmaf(d16, v, syn);
                syn = fmaf(carry, dlane1, syn);
                if (valid) {
                    const float d = o - syn * inv_tau;
                    acc = fmaf(d, d, acc);
                }
                carry = __shfl_sync(FULL, syn, 31);
            }
        }
    }

    // ---- block reduction of acc ----
    #pragma unroll
    for (int off = 16; off; off >>= 1)
        acc += __shfl_down_sync(FULL, acc, off);

    __shared__ float warp_sums[8];
    __shared__ bool  s_is_last;
    const int wib = threadIdx.x >> 5;
    if (lane == 0) warp_sums[wib] = acc;
    __syncthreads();

    if (threadIdx.x == 0) {
        const int nw = blockDim.x >> 5;
        float s = 0.0f;
        #pragma unroll
        for (int i = 0; i < 8; i++)
            if (i < nw) s += warp_sums[i];
        g_partials[blockIdx.x] = s;
        __threadfence();                               // partial visible before ticket
        unsigned old = atomicAdd(&g_ticket, 1u);
        s_is_last = (old == gridDim.x - 1);
    }
    __syncthreads();

    // ---- last block: reduce all partials, write scalar, reset ticket ----
    if (s_is_last) {
        volatile float* parts = g_partials;
        double s = 0.0;
        for (int i = threadIdx.x; i < (int)gridDim.x; i += blockDim.x)
            s += (double)parts[i];
        #pragma unroll
        for (int off = 16; off; off >>= 1)
            s += __shfl_down_sync(FULL, s, off);

        __shared__ double dsums[8];
        if (lane == 0) dsums[wib] = s;
        __syncthreads();
        if (threadIdx.x == 0) {
            const int nw = blockDim.x >> 5;
            double t = 0.0;
            #pragma unroll
            for (int i = 0; i < 8; i++)
                if (i < nw) t += dsums[i];
            out[0] = (float)(0.5 * t);
            g_ticket = 0;                              // deterministic for next replay
        }
    }
}

extern "C" void kernel_launch(void* const* d_in, const int* in_sizes, int n_in,
                              void* d_out, int out_size)
{
    const float* outputs = (const float*)d_in[0];
    const float* target  = (const float*)d_in[1];
    const int*   n_steps = (const int*)d_in[2];
    const int*   tau_s   = (const int*)d_in[3];
    float*       out     = (float*)d_out;

    const long long n_total = (long long)in_sizes[0];

    const int threads = 256;
    const int blocks  = 148 * 8;   // 1184 <= MAX_BLOCKS
    spike_loss_kernel<<<blocks, threads>>>(outputs, target, n_steps, tau_s, n_total, out);
}